// round 1
// baseline (speedup 1.0000x reference)
#include <cuda_runtime.h>
#include <math_constants.h>

// Problem constants
#define NTOK 32768      // 32 * 32 * 32 tokens
#define D    256        // embedding dim
#define K    1024       // codebook size
#define HW   1024       // H*W = 32*32
#define TM   128        // tokens per block tile
#define TK   128        // codes per k-tile
#define CC   8          // c-chunk staged in smem

// Scratch (no allocations allowed)
__device__ float  g_normE[K];
__device__ int    g_idx[NTOK];
__device__ double g_partial[128];

// ---------------------------------------------------------------------------
// K0: codebook squared norms
// ---------------------------------------------------------------------------
__global__ void k_norme(const float* __restrict__ E) {
    int k = blockIdx.x * blockDim.x + threadIdx.x;
    if (k < K) {
        const float* e = E + (size_t)k * D;
        float s = 0.f;
        #pragma unroll 8
        for (int c = 0; c < D; c++) s = fmaf(e[c], e[c], s);
        g_normE[k] = s;
    }
}

// ---------------------------------------------------------------------------
// K1: fused distance GEMM + argmin
//   dist[n][k] = (||x_n||^2 - 2*(x_n . e_k)) + ||e_k||^2   (ref rounding order)
//   argmin with first-index tie-break (strict <, ascending k)
// ---------------------------------------------------------------------------
__global__ void __launch_bounds__(256, 2) k_argmin(
    const float* __restrict__ X, const float* __restrict__ E,
    float* __restrict__ outIdxF, int writeIdxF)
{
    __shared__ float Xs[CC][TM];
    __shared__ float Es[CC][136];     // padded: kills transposed-store conflicts
    __shared__ float normXs[TM];
    __shared__ float normEs[TK];
    __shared__ float redv[TM][17];    // padded: conflict-free row reads
    __shared__ int   redi[TM][17];
    __shared__ float bestv[TM];
    __shared__ int   besti[TM];

    const int tid = threadIdx.x;
    const int tx  = tid & 15;         // token group (8 tokens)
    const int ty  = tid >> 4;         // code group (8 codes)
    const int tokenBase = blockIdx.x * TM;
    const int b   = tokenBase >> 10;          // batch (1024 tokens per image)
    const int hw0 = tokenBase & (HW - 1);
    const float* Xb = X + (size_t)b * (D * HW) + hw0;

    if (tid < TM) { bestv[tid] = CUDART_INF_F; besti[tid] = 0; }

    float nx[8];
    #pragma unroll
    for (int i = 0; i < 8; i++) nx[i] = 0.f;

    for (int k0 = 0; k0 < K; k0 += TK) {
        if (tid < TK) normEs[tid] = g_normE[k0 + tid];

        float acc[8][8];
        #pragma unroll
        for (int i = 0; i < 8; i++)
            #pragma unroll
            for (int j = 0; j < 8; j++) acc[i][j] = 0.f;

        for (int c0 = 0; c0 < D; c0 += CC) {
            __syncthreads();   // protect smem reuse (also orders normEs writes)
            // Stage X: Xs[cc][token] — coalesced 128-float rows
            #pragma unroll
            for (int p = 0; p < 4; p++) {
                int i = p * 256 + tid;
                int cc = i >> 7, col = i & 127;
                Xs[cc][col] = Xb[(size_t)(c0 + cc) * HW + col];
            }
            // Stage E: Es[cc][code] — 32B-contiguous reads per thread-octet
            #pragma unroll
            for (int p = 0; p < 4; p++) {
                int i = p * 256 + tid;
                int kk = i >> 3, cc = i & 7;
                Es[cc][kk] = E[(size_t)(k0 + kk) * D + c0 + cc];
            }
            __syncthreads();

            #pragma unroll
            for (int cc = 0; cc < CC; cc++) {
                float4 a0 = *(const float4*)&Xs[cc][tx * 8];
                float4 a1 = *(const float4*)&Xs[cc][tx * 8 + 4];
                float4 b0 = *(const float4*)&Es[cc][ty * 8];
                float4 b1 = *(const float4*)&Es[cc][ty * 8 + 4];
                float a[8]  = {a0.x, a0.y, a0.z, a0.w, a1.x, a1.y, a1.z, a1.w};
                float bb[8] = {b0.x, b0.y, b0.z, b0.w, b1.x, b1.y, b1.z, b1.w};
                if (k0 == 0 && ty == 0) {   // fold ||x||^2 into the first k-tile
                    #pragma unroll
                    for (int i = 0; i < 8; i++) nx[i] = fmaf(a[i], a[i], nx[i]);
                }
                #pragma unroll
                for (int i = 0; i < 8; i++)
                    #pragma unroll
                    for (int j = 0; j < 8; j++)
                        acc[i][j] = fmaf(a[i], bb[j], acc[i][j]);
            }
        }
        __syncthreads();
        if (k0 == 0 && ty == 0) {
            #pragma unroll
            for (int i = 0; i < 8; i++) normXs[tx * 8 + i] = nx[i];
        }
        __syncthreads();

        // Per-thread min over its 8 codes (ascending j, strict < => first idx)
        #pragma unroll
        for (int i = 0; i < 8; i++) {
            float nX = normXs[tx * 8 + i];
            float bv = CUDART_INF_F; int bk = 0;
            #pragma unroll
            for (int j = 0; j < 8; j++) {
                // Match reference rounding: (normX - 2*s) + normE, no contraction
                float d = __fadd_rn(__fsub_rn(nX, __fmul_rn(2.0f, acc[i][j])),
                                    normEs[ty * 8 + j]);
                if (d < bv) { bv = d; bk = k0 + ty * 8 + j; }
            }
            redv[tx * 8 + i][ty] = bv;
            redi[tx * 8 + i][ty] = bk;
        }
        __syncthreads();

        // Cross-ty reduce (ascending ty = ascending code) + running best
        if (tid < TM) {
            float bv = bestv[tid]; int bk = besti[tid];
            #pragma unroll
            for (int t = 0; t < 16; t++) {
                float v = redv[tid][t];
                if (v < bv) { bv = v; bk = redi[tid][t]; }
            }
            bestv[tid] = bv; besti[tid] = bk;
        }
    }
    __syncthreads();
    if (tid < TM) {
        int n = tokenBase + tid;
        g_idx[n] = besti[tid];
        if (writeIdxF) outIdxF[n] = (float)besti[tid];
    }
}

// ---------------------------------------------------------------------------
// K2: gather quantized output (NCHW) + deterministic MSE partial sums
// ---------------------------------------------------------------------------
__global__ void k_gather(const float* __restrict__ X, const float* __restrict__ E,
                         float* __restrict__ Q, int writeQ)
{
    __shared__ double sred[256];
    const int tid = threadIdx.x;
    const int n   = blockIdx.x * 256 + tid;
    const int b   = n >> 10;
    const int hw  = n & (HW - 1);
    const float* xb = X + (size_t)b * (D * HW) + hw;
    float*       qb = Q + (size_t)b * (D * HW) + hw;
    const float* e  = E + (size_t)g_idx[n] * D;

    double s = 0.0;
    #pragma unroll 4
    for (int c = 0; c < D; c++) {
        float q = __ldg(&e[c]);                 // scattered but L2-resident (1 MB)
        float x = xb[(size_t)c * HW];           // coalesced across the warp
        if (writeQ) qb[(size_t)c * HW] = q;     // coalesced
        float dd = q - x;
        s = fma((double)dd, (double)dd, s);
    }
    sred[tid] = s;
    __syncthreads();
    for (int off = 128; off > 0; off >>= 1) {   // deterministic tree
        if (tid < off) sred[tid] += sred[tid + off];
        __syncthreads();
    }
    if (tid == 0) g_partial[blockIdx.x] = sred[0];
}

// ---------------------------------------------------------------------------
// K3: finalize loss = e + 0.25*e  (q_latent == e_latent in fwd)
// ---------------------------------------------------------------------------
__global__ void k_loss(float* __restrict__ out, int lossOff)
{
    if (threadIdx.x == 0) {
        double s = 0.0;
        for (int i = 0; i < 128; i++) s += g_partial[i];
        float e = (float)(s / (double)((size_t)NTOK * D));
        out[lossOff] = e + 0.25f * e;
    }
}

// ---------------------------------------------------------------------------
extern "C" void kernel_launch(void* const* d_in, const int* in_sizes, int n_in,
                              void* d_out, int out_size)
{
    const float* X = (const float*)d_in[0];   // inputs  [32,256,32,32]
    const float* E = (const float*)d_in[1];   // codebook [1024,256]
    float* out = (float*)d_out;

    const int qn = NTOK * D;                  // 8388608 quantized elements

    // Figure out output layout from out_size (robust to variants)
    int writeQ = 0, lossOff = -1, idxOff = -1;
    if (out_size >= qn) writeQ = 1;
    if (out_size == qn + 1 + NTOK) { lossOff = qn; idxOff = qn + 1; }
    else if (out_size == qn + 1)   { lossOff = qn; }
    else if (out_size == qn + NTOK){ idxOff = qn; }
    else if (out_size == NTOK)     { idxOff = 0; writeQ = 0; }

    k_norme<<<8, 128>>>(E);
    k_argmin<<<NTOK / TM, 256>>>(X, E,
                                 (idxOff >= 0) ? (out + idxOff) : out,
                                 (idxOff >= 0) ? 1 : 0);
    if (writeQ || lossOff >= 0)
        k_gather<<<NTOK / 256, 256>>>(X, E, out, writeQ);
    if (lossOff >= 0)
        k_loss<<<1, 32>>>(out, lossOff);
}

// round 4
// speedup vs baseline: 1.3440x; 1.3440x over previous
#include <cuda_runtime.h>
#include <cuda_bf16.h>
#include <math_constants.h>
#include <cstdint>

// ---------------- problem constants ----------------
#define NTOK 32768      // 32*32*32 tokens
#define D    256        // embedding dim
#define K    1024       // codebook size
#define HW   1024       // H*W
#define TM   128        // tokens per CTA tile
#define TN   128        // codes per CTA tile
#define KCH  64         // dims per pipeline stage
#define NPARTS 6        // bf16x6 split products
#define NITER (NPARTS * 4)   // 24 stages (4 x 64 dims per part)
#define NSTG 3          // cp.async stages
#define STG_BYTES 32768 // A 16KB + B 16KB per stage

// ---------------- device scratch (no allocations allowed) ----------------
__device__ __align__(256) __nv_bfloat16 g_Xh[NTOK * D];
__device__ __align__(256) __nv_bfloat16 g_Xm[NTOK * D];
__device__ __align__(256) __nv_bfloat16 g_Xl[NTOK * D];
__device__ __align__(256) __nv_bfloat16 g_Eh[K * D];
__device__ __align__(256) __nv_bfloat16 g_Em[K * D];
__device__ __align__(256) __nv_bfloat16 g_El[K * D];
__device__ float  g_normX[NTOK];
__device__ float  g_normE[K];
__device__ unsigned long long g_best[NTOK];
__device__ double g_partial[128];

__device__ __forceinline__ uint32_t smem_u32(const void* p) {
    uint32_t a;
    asm("{ .reg .u64 t; cvta.to.shared.u64 t, %1; cvt.u32.u64 %0, t; }" : "=r"(a) : "l"(p));
    return a;
}
#define CP_ASYNC16(saddr, gptr) \
    asm volatile("cp.async.cg.shared.global [%0], [%1], 16;" :: "r"(saddr), "l"(gptr))
#define CP_COMMIT() asm volatile("cp.async.commit_group;" ::: "memory")
#define CP_WAIT1()  asm volatile("cp.async.wait_group 1;" ::: "memory")
#define LDSM_X4(r0, r1, r2, r3, a) \
    asm volatile("ldmatrix.sync.aligned.m8n8.x4.shared.b16 {%0,%1,%2,%3}, [%4];" \
        : "=r"(r0), "=r"(r1), "=r"(r2), "=r"(r3) : "r"(a))
#define MMA_BF16(d, a, b0v, b1v) \
    asm volatile("mma.sync.aligned.m16n8k16.row.col.f32.bf16.bf16.f32 " \
        "{%0,%1,%2,%3}, {%4,%5,%6,%7}, {%8,%9}, {%0,%1,%2,%3};" \
        : "+f"((d)[0]), "+f"((d)[1]), "+f"((d)[2]), "+f"((d)[3]) \
        : "r"((a)[0]), "r"((a)[1]), "r"((a)[2]), "r"((a)[3]), "r"(b0v), "r"(b1v))

// smem addr within a 128-row x 128B tile, SW128 swizzled (u = 16B unit 0..7)
__device__ __forceinline__ uint32_t swaddr(int row, int u) {
    return (uint32_t)(row * 128 + ((u ^ (row & 7)) << 4));
}

// ---------------------------------------------------------------------------
// K0: codebook 3-way bf16 split + squared norms
// ---------------------------------------------------------------------------
__global__ void k_prep_e(const float* __restrict__ E) {
    int k = blockIdx.x * blockDim.x + threadIdx.x;
    if (k >= K) return;
    const float* e = E + (size_t)k * D;
    float s = 0.f;
    #pragma unroll 8
    for (int c = 0; c < D; c++) {
        float x = e[c];
        s = fmaf(x, x, s);
        __nv_bfloat16 h = __float2bfloat16(x);
        float r1 = x - __bfloat162float(h);
        __nv_bfloat16 m = __float2bfloat16(r1);
        float r2 = r1 - __bfloat162float(m);
        g_Eh[(size_t)k * D + c] = h;
        g_Em[(size_t)k * D + c] = m;
        g_El[(size_t)k * D + c] = __float2bfloat16(r2);
    }
    g_normE[k] = s;
}

// ---------------------------------------------------------------------------
// K1: transpose X (NCHW -> token-major) + 3-way bf16 split + ||x||^2 + reset
// ---------------------------------------------------------------------------
__global__ void k_split_x(const float* __restrict__ X) {
    __shared__ float tile[D][33];
    __shared__ float psum[32][9];
    const int tid = threadIdx.x;
    const int b   = blockIdx.x >> 5;
    const int hw0 = (blockIdx.x & 31) * 32;
    const float* Xb = X + (size_t)b * (D * HW) + hw0;

    if (tid < 32) g_best[b * HW + hw0 + tid] = ~0ull;   // reset argmin keys

    {
        int w = tid >> 5, lane = tid & 31;
        #pragma unroll
        for (int c = w; c < D; c += 8) tile[c][lane] = Xb[(size_t)c * HW + lane];
    }
    __syncthreads();

    const int tt = tid >> 3;          // token 0..31
    const int cc = tid & 7;           // channel block
    const int n  = b * HW + hw0 + tt;
    float s = 0.f;
    #pragma unroll
    for (int c8 = 0; c8 < 4; c8++) {
        uint32_t hp[4], mp[4], lp[4];
        #pragma unroll
        for (int q = 0; q < 4; q++) {
            int c0 = cc * 32 + c8 * 8 + q * 2;
            float x0 = tile[c0][tt], x1 = tile[c0 + 1][tt];
            s = fmaf(x0, x0, s); s = fmaf(x1, x1, s);
            __nv_bfloat16 h0 = __float2bfloat16(x0), h1 = __float2bfloat16(x1);
            float r10 = x0 - __bfloat162float(h0), r11 = x1 - __bfloat162float(h1);
            __nv_bfloat16 m0 = __float2bfloat16(r10), m1 = __float2bfloat16(r11);
            float r20 = r10 - __bfloat162float(m0), r21 = r11 - __bfloat162float(m1);
            __nv_bfloat16 l0 = __float2bfloat16(r20), l1 = __float2bfloat16(r21);
            hp[q] = (uint32_t)*(uint16_t*)&h0 | ((uint32_t)*(uint16_t*)&h1 << 16);
            mp[q] = (uint32_t)*(uint16_t*)&m0 | ((uint32_t)*(uint16_t*)&m1 << 16);
            lp[q] = (uint32_t)*(uint16_t*)&l0 | ((uint32_t)*(uint16_t*)&l1 << 16);
        }
        *(uint4*)&g_Xh[(size_t)n * D + cc * 32 + c8 * 8] = make_uint4(hp[0], hp[1], hp[2], hp[3]);
        *(uint4*)&g_Xm[(size_t)n * D + cc * 32 + c8 * 8] = make_uint4(mp[0], mp[1], mp[2], mp[3]);
        *(uint4*)&g_Xl[(size_t)n * D + cc * 32 + c8 * 8] = make_uint4(lp[0], lp[1], lp[2], lp[3]);
    }
    psum[tt][cc] = s;
    __syncthreads();
    if (cc == 0) {
        float t = 0.f;
        #pragma unroll
        for (int q = 0; q < 8; q++) t += psum[tt][q];
        g_normX[n] = t;
    }
}

// ---------------------------------------------------------------------------
// K2: bf16x6-split HMMA GEMM (K=1536 concat) + fused argmin
//   dot = Xh.Em + Xm.Eh + Xm.Em + Xh.El + Xl.Eh + Xh.Eh
//   (small parts first: keeps fp32 accumulator rounding noise ~7e-9)
// ---------------------------------------------------------------------------
__global__ void __launch_bounds__(256, 2) k_vq()
{
    extern __shared__ char smem[];                 // NSTG * (A 16KB | B 16KB)
    __shared__ unsigned long long bestS[TM];
    __shared__ float nXs[TM], nEs[TN];

    const int tid  = threadIdx.x;
    const int bid  = blockIdx.x;
    const int tokenBase = (bid >> 3) * TM;
    const int codeBase  = (bid & 7) * TN;

    if (tid < TM) {
        bestS[tid] = ~0ull;
        nXs[tid] = g_normX[tokenBase + tid];
        nEs[tid] = g_normE[codeBase + tid];
    }

    const uint32_t sb = smem_u32(smem);
    const int ldr = tid >> 3, lds = tid & 7;       // cp.async row / 16B-seg

    // part tables: {hm, mh, mm, hl, lh, hh}
    auto issue = [&](int s) {
        const int part = s >> 2, koff = (s & 3) * KCH;
        const __nv_bfloat16* Asrc;
        const __nv_bfloat16* Bsrc;
        switch (part) {
            case 0: Asrc = g_Xh; Bsrc = g_Em; break;
            case 1: Asrc = g_Xm; Bsrc = g_Eh; break;
            case 2: Asrc = g_Xm; Bsrc = g_Em; break;
            case 3: Asrc = g_Xh; Bsrc = g_El; break;
            case 4: Asrc = g_Xl; Bsrc = g_Eh; break;
            default: Asrc = g_Xh; Bsrc = g_Eh; break;
        }
        const uint32_t Ab = sb + (s % NSTG) * STG_BYTES;
        const uint32_t Bb = Ab + 16384;
        #pragma unroll
        for (int i = 0; i < 4; i++) {
            int r = ldr + i * 32;
            uint32_t so = swaddr(r, lds);
            CP_ASYNC16(Ab + so, Asrc + (size_t)(tokenBase + r) * D + koff + lds * 8);
            CP_ASYNC16(Bb + so, Bsrc + (size_t)(codeBase  + r) * D + koff + lds * 8);
        }
        CP_COMMIT();
    };

    issue(0); issue(1);

    const int lane = tid & 31, wid = tid >> 5;
    const int mrow0 = (wid & 1) * 64;              // warp M offset (2 warps)
    const int ncol0 = (wid >> 1) * 32;             // warp N offset (4 warps)
    const int lrow  = lane & 15, lhalf = lane >> 4;

    float acc[4][4][4];
    #pragma unroll
    for (int m = 0; m < 4; m++)
        #pragma unroll
        for (int n = 0; n < 4; n++)
            #pragma unroll
            for (int q = 0; q < 4; q++) acc[m][n][q] = 0.f;

    for (int s = 0; s < NITER; s++) {
        CP_WAIT1();
        __syncthreads();
        if (s + 2 < NITER) issue(s + 2);

        const uint32_t Ab = sb + (s % NSTG) * STG_BYTES;
        const uint32_t Bb = Ab + 16384;

        #pragma unroll
        for (int k16 = 0; k16 < 4; k16++) {
            const int u = k16 * 2 + lhalf;
            uint32_t a[4][4], bfr[2][4];
            #pragma unroll
            for (int m = 0; m < 4; m++) {
                int r = mrow0 + m * 16 + lrow;
                LDSM_X4(a[m][0], a[m][1], a[m][2], a[m][3], Ab + swaddr(r, u));
            }
            #pragma unroll
            for (int nb = 0; nb < 2; nb++) {
                int r = ncol0 + nb * 16 + lrow;
                LDSM_X4(bfr[nb][0], bfr[nb][1], bfr[nb][2], bfr[nb][3], Bb + swaddr(r, u));
            }
            #pragma unroll
            for (int m = 0; m < 4; m++)
                #pragma unroll
                for (int n = 0; n < 4; n++)
                    MMA_BF16(acc[m][n], a[m], bfr[n >> 1][n & 1], bfr[n >> 1][2 + (n & 1)]);
        }
    }

    // ---- epilogue: reference-rounded distance + packed argmin
    #pragma unroll
    for (int m = 0; m < 4; m++) {
        #pragma unroll
        for (int rr = 0; rr < 2; rr++) {
            const int row = mrow0 + m * 16 + (lane >> 2) + rr * 8;
            const float nX = nXs[row];
            unsigned long long key = ~0ull;
            #pragma unroll
            for (int n = 0; n < 4; n++) {
                #pragma unroll
                for (int cc2 = 0; cc2 < 2; cc2++) {
                    const int col = ncol0 + n * 8 + 2 * (lane & 3) + cc2;
                    float sdot = acc[m][n][rr * 2 + cc2];
                    float d = __fadd_rn(__fsub_rn(nX, __fmul_rn(2.0f, sdot)), nEs[col]);
                    unsigned long long kk =
                        ((unsigned long long)__float_as_uint(d) << 32) |
                        (unsigned)(codeBase + col);
                    key = (kk < key) ? kk : key;
                }
            }
            atomicMin(&bestS[row], key);
        }
    }
    __syncthreads();
    if (tid < TM) atomicMin(&g_best[tokenBase + tid], bestS[tid]);
}

// ---------------------------------------------------------------------------
// K3: gather quantized output + idx output + deterministic MSE partials
// ---------------------------------------------------------------------------
__global__ void k_gather(const float* __restrict__ X, const float* __restrict__ E,
                         float* __restrict__ Q, int writeQ,
                         float* __restrict__ outIdxF, int writeIdx)
{
    __shared__ double sred[256];
    const int tid = threadIdx.x;
    const int n   = blockIdx.x * 256 + tid;
    const int b   = n >> 10;
    const int hw  = n & (HW - 1);
    const float* xb = X + (size_t)b * (D * HW) + hw;
    float*       qb = Q + (size_t)b * (D * HW) + hw;
    const int idx = (int)(unsigned)(g_best[n] & 0xFFFFFFFFull);
    const float* e = E + (size_t)idx * D;

    if (writeIdx) outIdxF[n] = (float)idx;

    double s = 0.0;
    #pragma unroll 4
    for (int c = 0; c < D; c++) {
        float q = __ldg(&e[c]);
        float x = xb[(size_t)c * HW];
        if (writeQ) qb[(size_t)c * HW] = q;
        float dd = q - x;
        s = fma((double)dd, (double)dd, s);
    }
    sred[tid] = s;
    __syncthreads();
    for (int off = 128; off > 0; off >>= 1) {
        if (tid < off) sred[tid] += sred[tid + off];
        __syncthreads();
    }
    if (tid == 0) g_partial[blockIdx.x] = sred[0];
}

__global__ void k_loss(float* __restrict__ out, int lossOff)
{
    __shared__ double sd[128];
    int t = threadIdx.x;
    sd[t] = g_partial[t];
    __syncthreads();
    for (int o = 64; o > 0; o >>= 1) {
        if (t < o) sd[t] += sd[t + o];
        __syncthreads();
    }
    if (t == 0) {
        float e = (float)(sd[0] / (double)((size_t)NTOK * D));
        out[lossOff] = e + 0.25f * e;
    }
}

// ---------------------------------------------------------------------------
extern "C" void kernel_launch(void* const* d_in, const int* in_sizes, int n_in,
                              void* d_out, int out_size)
{
    const float* X = (const float*)d_in[0];   // [32,256,32,32]
    const float* E = (const float*)d_in[1];   // [1024,256]
    float* out = (float*)d_out;

    const int qn = NTOK * D;
    int writeQ = 0, lossOff = -1, idxOff = -1;
    if (out_size >= qn) writeQ = 1;
    if (out_size == qn + 1 + NTOK) { lossOff = qn; idxOff = qn + 1; }
    else if (out_size == qn + 1)   { lossOff = qn; }
    else if (out_size == qn + NTOK){ idxOff = qn; }
    else if (out_size == NTOK)     { idxOff = 0; writeQ = 0; }

    cudaFuncSetAttribute(k_vq, cudaFuncAttributeMaxDynamicSharedMemorySize,
                         NSTG * STG_BYTES);

    k_prep_e<<<8, 128>>>(E);
    k_split_x<<<NTOK / 32, 256>>>(X);
    k_vq<<<(NTOK / TM) * (K / TN), 256, NSTG * STG_BYTES>>>();
    k_gather<<<NTOK / 256, 256>>>(X, E, out, writeQ,
                                  (idxOff >= 0) ? (out + idxOff) : out,
                                  (idxOff >= 0) ? 1 : 0);
    if (lossOff >= 0)
        k_loss<<<1, 128>>>(out, lossOff);
}

// round 5
// speedup vs baseline: 1.7225x; 1.2816x over previous
#include <cuda_runtime.h>
#include <cuda_fp16.h>
#include <math_constants.h>
#include <cstdint>

// ---------------- problem constants ----------------
#define NTOK 32768      // 32*32*32 tokens
#define D    256        // embedding dim
#define K    1024       // codebook size
#define HW   1024       // H*W
#define TM   128        // tokens per CTA tile
#define TN   128        // codes per CTA tile
#define KCH  64         // dims per pipeline stage
#define NITER 12        // 3 parts x 4 chunks of 64 dims
#define NSTG 3          // cp.async stages
#define STG_BYTES 32768 // A 16KB + B 16KB per stage
#define SPLIT_SCALE 2048.0f
#define SPLIT_INV   4.8828125e-4f   // 2^-11, exact
#define FP16_MIN_NORM 6.103515625e-5f

// ---------------- device scratch (no allocations allowed) ----------------
__device__ __align__(256) __half g_Xh[NTOK * D];
__device__ __align__(256) __half g_Xl[NTOK * D];   // (x - h) * 2^11
__device__ __align__(256) __half g_Eh[K * D];
__device__ __align__(256) __half g_El[K * D];      // (e - h) * 2^11
__device__ float  g_normX[NTOK];
__device__ float  g_normE[K];
__device__ unsigned long long g_best[NTOK];
__device__ double g_partial[1024];

__device__ __forceinline__ uint32_t smem_u32(const void* p) {
    uint32_t a;
    asm("{ .reg .u64 t; cvta.to.shared.u64 t, %1; cvt.u32.u64 %0, t; }" : "=r"(a) : "l"(p));
    return a;
}
#define CP_ASYNC16(saddr, gptr) \
    asm volatile("cp.async.cg.shared.global [%0], [%1], 16;" :: "r"(saddr), "l"(gptr))
#define CP_COMMIT() asm volatile("cp.async.commit_group;" ::: "memory")
#define CP_WAIT1()  asm volatile("cp.async.wait_group 1;" ::: "memory")
#define LDSM_X4(r0, r1, r2, r3, a) \
    asm volatile("ldmatrix.sync.aligned.m8n8.x4.shared.b16 {%0,%1,%2,%3}, [%4];" \
        : "=r"(r0), "=r"(r1), "=r"(r2), "=r"(r3) : "r"(a))
#define MMA_F16(d, a, b0v, b1v) \
    asm volatile("mma.sync.aligned.m16n8k16.row.col.f32.f16.f16.f32 " \
        "{%0,%1,%2,%3}, {%4,%5,%6,%7}, {%8,%9}, {%0,%1,%2,%3};" \
        : "+f"((d)[0]), "+f"((d)[1]), "+f"((d)[2]), "+f"((d)[3]) \
        : "r"((a)[0]), "r"((a)[1]), "r"((a)[2]), "r"((a)[3]), "r"(b0v), "r"(b1v))

// smem addr within a 128-row x 128B tile, SW128 swizzled (u = 16B unit 0..7)
__device__ __forceinline__ uint32_t swaddr(int row, int u) {
    return (uint32_t)(row * 128 + ((u ^ (row & 7)) << 4));
}

// split x into fp16 h (subnormal-flushed) + fp16 l = (x-h)*2^11
__device__ __forceinline__ void split2(float x, __half& h, __half& l) {
    __half hh = __float2half_rn(x);
    float hf = __half2float(hh);
    if (fabsf(hf) < FP16_MIN_NORM) { hh = __float2half_rn(0.f); hf = 0.f; }
    h = hh;
    l = __float2half_rn((x - hf) * SPLIT_SCALE);
}

// ---------------------------------------------------------------------------
// K0: codebook fp16 2-way split + squared norms
// ---------------------------------------------------------------------------
__global__ void k_prep_e(const float* __restrict__ E) {
    int k = blockIdx.x * blockDim.x + threadIdx.x;
    if (k >= K) return;
    const float* e = E + (size_t)k * D;
    float s = 0.f;
    #pragma unroll 8
    for (int c = 0; c < D; c++) {
        float x = e[c];
        s = fmaf(x, x, s);
        __half h, l;
        split2(x, h, l);
        g_Eh[(size_t)k * D + c] = h;
        g_El[(size_t)k * D + c] = l;
    }
    g_normE[k] = s;
}

// ---------------------------------------------------------------------------
// K1: transpose X (NCHW -> token-major) + fp16 split + ||x||^2 + reset
// ---------------------------------------------------------------------------
__global__ void k_split_x(const float* __restrict__ X) {
    __shared__ float tile[D][33];
    __shared__ float psum[32][9];
    const int tid = threadIdx.x;
    const int b   = blockIdx.x >> 5;
    const int hw0 = (blockIdx.x & 31) * 32;
    const float* Xb = X + (size_t)b * (D * HW) + hw0;

    if (tid < 32) g_best[b * HW + hw0 + tid] = ~0ull;   // reset argmin keys

    {
        int w = tid >> 5, lane = tid & 31;
        #pragma unroll
        for (int c = w; c < D; c += 8) tile[c][lane] = Xb[(size_t)c * HW + lane];
    }
    __syncthreads();

    const int tt = tid >> 3;          // token 0..31
    const int cc = tid & 7;           // channel block
    const int n  = b * HW + hw0 + tt;
    float s = 0.f;
    #pragma unroll
    for (int c8 = 0; c8 < 4; c8++) {
        uint32_t hp[4], lp[4];
        #pragma unroll
        for (int q = 0; q < 4; q++) {
            int c0 = cc * 32 + c8 * 8 + q * 2;
            float x0 = tile[c0][tt], x1 = tile[c0 + 1][tt];
            s = fmaf(x0, x0, s); s = fmaf(x1, x1, s);
            __half h0, l0, h1, l1;
            split2(x0, h0, l0);
            split2(x1, h1, l1);
            hp[q] = (uint32_t)*(uint16_t*)&h0 | ((uint32_t)*(uint16_t*)&h1 << 16);
            lp[q] = (uint32_t)*(uint16_t*)&l0 | ((uint32_t)*(uint16_t*)&l1 << 16);
        }
        *(uint4*)&g_Xh[(size_t)n * D + cc * 32 + c8 * 8] = make_uint4(hp[0], hp[1], hp[2], hp[3]);
        *(uint4*)&g_Xl[(size_t)n * D + cc * 32 + c8 * 8] = make_uint4(lp[0], lp[1], lp[2], lp[3]);
    }
    psum[tt][cc] = s;
    __syncthreads();
    if (cc == 0) {
        float t = 0.f;
        #pragma unroll
        for (int q = 0; q < 8; q++) t += psum[tt][q];
        g_normX[n] = t;
    }
}

// ---------------------------------------------------------------------------
// K2: fp16x2-split HMMA GEMM + fused argmin
//   stages 0-7:  (Xh.El + Xl.Eh) * 2^11   -> acc *= 2^-11
//   stages 8-11:  Xh.Eh accumulated on top (small parts first)
// ---------------------------------------------------------------------------
__global__ void __launch_bounds__(256, 2) k_vq()
{
    extern __shared__ char smem[];                 // NSTG * (A 16KB | B 16KB)
    __shared__ unsigned long long bestS[TM];
    __shared__ float nXs[TM], nEs[TN];

    const int tid  = threadIdx.x;
    const int bid  = blockIdx.x;
    const int tokenBase = (bid >> 3) * TM;
    const int codeBase  = (bid & 7) * TN;

    if (tid < TM) {
        bestS[tid] = ~0ull;
        nXs[tid] = g_normX[tokenBase + tid];
        nEs[tid] = g_normE[codeBase + tid];
    }

    const uint32_t sb = smem_u32(smem);
    const int ldr = tid >> 3, lds = tid & 7;       // cp.async row / 16B-seg

    // parts: {0: Xh.El, 1: Xl.Eh, 2: Xh.Eh}
    auto issue = [&](int s) {
        const int part = s >> 2, koff = (s & 3) * KCH;
        const __half* Asrc = (part == 1) ? g_Xl : g_Xh;
        const __half* Bsrc = (part == 0) ? g_El : g_Eh;
        const uint32_t Ab = sb + (s % NSTG) * STG_BYTES;
        const uint32_t Bb = Ab + 16384;
        #pragma unroll
        for (int i = 0; i < 4; i++) {
            int r = ldr + i * 32;
            uint32_t so = swaddr(r, lds);
            CP_ASYNC16(Ab + so, Asrc + (size_t)(tokenBase + r) * D + koff + lds * 8);
            CP_ASYNC16(Bb + so, Bsrc + (size_t)(codeBase  + r) * D + koff + lds * 8);
        }
        CP_COMMIT();
    };

    issue(0); issue(1);

    const int lane = tid & 31, wid = tid >> 5;
    const int mrow0 = (wid & 1) * 64;              // warp M offset (2 warps)
    const int ncol0 = (wid >> 1) * 32;             // warp N offset (4 warps)
    const int lrow  = lane & 15, lhalf = lane >> 4;

    float acc[4][4][4];
    #pragma unroll
    for (int m = 0; m < 4; m++)
        #pragma unroll
        for (int n = 0; n < 4; n++)
            #pragma unroll
            for (int q = 0; q < 4; q++) acc[m][n][q] = 0.f;

    for (int s = 0; s < NITER; s++) {
        CP_WAIT1();
        __syncthreads();
        if (s + 2 < NITER) issue(s + 2);

        if (s == 8) {   // rescale the low-part partial dot: exact 2^-11
            #pragma unroll
            for (int m = 0; m < 4; m++)
                #pragma unroll
                for (int n = 0; n < 4; n++)
                    #pragma unroll
                    for (int q = 0; q < 4; q++) acc[m][n][q] *= SPLIT_INV;
        }

        const uint32_t Ab = sb + (s % NSTG) * STG_BYTES;
        const uint32_t Bb = Ab + 16384;

        #pragma unroll
        for (int k16 = 0; k16 < 4; k16++) {
            const int u = k16 * 2 + lhalf;
            uint32_t a[4][4], bfr[2][4];
            #pragma unroll
            for (int m = 0; m < 4; m++) {
                int r = mrow0 + m * 16 + lrow;
                LDSM_X4(a[m][0], a[m][1], a[m][2], a[m][3], Ab + swaddr(r, u));
            }
            #pragma unroll
            for (int nb = 0; nb < 2; nb++) {
                int r = ncol0 + nb * 16 + lrow;
                LDSM_X4(bfr[nb][0], bfr[nb][1], bfr[nb][2], bfr[nb][3], Bb + swaddr(r, u));
            }
            #pragma unroll
            for (int m = 0; m < 4; m++)
                #pragma unroll
                for (int n = 0; n < 4; n++)
                    MMA_F16(acc[m][n], a[m], bfr[n >> 1][n & 1], bfr[n >> 1][2 + (n & 1)]);
        }
    }

    // ---- epilogue: reference-rounded distance + packed argmin
    #pragma unroll
    for (int m = 0; m < 4; m++) {
        #pragma unroll
        for (int rr = 0; rr < 2; rr++) {
            const int row = mrow0 + m * 16 + (lane >> 2) + rr * 8;
            const float nX = nXs[row];
            unsigned long long key = ~0ull;
            #pragma unroll
            for (int n = 0; n < 4; n++) {
                #pragma unroll
                for (int cc2 = 0; cc2 < 2; cc2++) {
                    const int col = ncol0 + n * 8 + 2 * (lane & 3) + cc2;
                    float sdot = acc[m][n][rr * 2 + cc2];
                    float d = __fadd_rn(__fsub_rn(nX, __fmul_rn(2.0f, sdot)), nEs[col]);
                    unsigned long long kk =
                        ((unsigned long long)__float_as_uint(d) << 32) |
                        (unsigned)(codeBase + col);
                    key = (kk < key) ? kk : key;
                }
            }
            atomicMin(&bestS[row], key);
        }
    }
    __syncthreads();
    if (tid < TM) atomicMin(&g_best[tokenBase + tid], bestS[tid]);
}

// ---------------------------------------------------------------------------
// K3: gather quantized output + idx output + deterministic MSE partials
//   grid 1024: 8 channel-chunks x 128 token-blocks; 32 channels per thread
// ---------------------------------------------------------------------------
__global__ void k_gather(const float* __restrict__ X, const float* __restrict__ E,
                         float* __restrict__ Q, int writeQ,
                         float* __restrict__ outIdxF, int writeIdx)
{
    __shared__ double sred[256];
    const int tid = threadIdx.x;
    const int cb  = blockIdx.x >> 7;          // channel chunk 0..7
    const int n   = (blockIdx.x & 127) * 256 + tid;
    const int b   = n >> 10;
    const int hw  = n & (HW - 1);
    const int ch0 = cb * 32;
    const float* xb = X + (size_t)b * (D * HW) + (size_t)ch0 * HW + hw;
    float*       qb = Q + (size_t)b * (D * HW) + (size_t)ch0 * HW + hw;
    const int idx = (int)(unsigned)(g_best[n] & 0xFFFFFFFFull);
    const float* e = E + (size_t)idx * D + ch0;

    if (writeIdx && cb == 0) outIdxF[n] = (float)idx;

    double s = 0.0;
    #pragma unroll
    for (int c4 = 0; c4 < 8; c4++) {
        float4 q4 = *(const float4*)(e + c4 * 4);
        float qv[4] = {q4.x, q4.y, q4.z, q4.w};
        #pragma unroll
        for (int j = 0; j < 4; j++) {
            int c = c4 * 4 + j;
            float x = xb[(size_t)c * HW];
            if (writeQ) qb[(size_t)c * HW] = qv[j];
            float dd = qv[j] - x;
            s = fma((double)dd, (double)dd, s);
        }
    }
    sred[tid] = s;
    __syncthreads();
    for (int off = 128; off > 0; off >>= 1) {
        if (tid < off) sred[tid] += sred[tid + off];
        __syncthreads();
    }
    if (tid == 0) g_partial[blockIdx.x] = sred[0];
}

__global__ void k_loss(float* __restrict__ out, int lossOff)
{
    __shared__ double sd[256];
    int t = threadIdx.x;
    double s = 0.0;
    #pragma unroll
    for (int i = 0; i < 4; i++) s += g_partial[t * 4 + i];
    sd[t] = s;
    __syncthreads();
    for (int o = 128; o > 0; o >>= 1) {
        if (t < o) sd[t] += sd[t + o];
        __syncthreads();
    }
    if (t == 0) {
        float e = (float)(sd[0] / (double)((size_t)NTOK * D));
        out[lossOff] = e + 0.25f * e;
    }
}

// ---------------------------------------------------------------------------
extern "C" void kernel_launch(void* const* d_in, const int* in_sizes, int n_in,
                              void* d_out, int out_size)
{
    const float* X = (const float*)d_in[0];   // [32,256,32,32]
    const float* E = (const float*)d_in[1];   // [1024,256]
    float* out = (float*)d_out;

    const int qn = NTOK * D;
    int writeQ = 0, lossOff = -1, idxOff = -1;
    if (out_size >= qn) writeQ = 1;
    if (out_size == qn + 1 + NTOK) { lossOff = qn; idxOff = qn + 1; }
    else if (out_size == qn + 1)   { lossOff = qn; }
    else if (out_size == qn + NTOK){ idxOff = qn; }
    else if (out_size == NTOK)     { idxOff = 0; writeQ = 0; }

    cudaFuncSetAttribute(k_vq, cudaFuncAttributeMaxDynamicSharedMemorySize,
                         NSTG * STG_BYTES);

    k_prep_e<<<8, 128>>>(E);
    k_split_x<<<NTOK / 32, 256>>>(X);
    k_vq<<<(NTOK / TM) * (K / TN), 256, NSTG * STG_BYTES>>>();
    k_gather<<<1024, 256>>>(X, E, out, writeQ,
                            (idxOff >= 0) ? (out + idxOff) : out,
                            (idxOff >= 0) ? 1 : 0);
    if (lossOff >= 0)
        k_loss<<<1, 256>>>(out, lossOff);
}

// round 7
// speedup vs baseline: 2.4053x; 1.3963x over previous
#include <cuda_runtime.h>
#include <cuda_fp16.h>
#include <math_constants.h>
#include <cstdint>

// ---------------- problem constants ----------------
#define NTOK 32768      // 32*32*32 tokens
#define D    256        // embedding dim
#define K    1024       // codebook size
#define HW   1024       // H*W
#define TM   128        // tokens per CTA tile
#define TN   128        // codes per CTA tile
#define KCH  64         // dims per pipeline stage
#define NITER 4         // 4 chunks of 64 dims (hh only)
#define NSTG 3          // cp.async stages
#define STG_BYTES 32768 // A 16KB + B 16KB per stage
#define CAND_CAP 32
#define ESCL      1024.0f          // 2^10 exact
#define ESCL_INV  9.765625e-4f     // 2^-10 exact
// |d_hh - d_exact| <= 4*2^-11*||x||*||e||max + slack
#define T_COEF  1.98e-3f
#define T_SLACK 2.0e-4f

// ---------------- device scratch (no allocations allowed) ----------------
__device__ __align__(256) __half g_Xh[NTOK * D];
__device__ __align__(256) __half g_Eh[K * D];      // fl16(e * 2^10)
__device__ __align__(256) float  g_Xt[NTOK * D];   // fp32 token-major X
__device__ float  g_normX[NTOK];
__device__ float  g_normE[K];
__device__ float  g_maxEblk[8];
__device__ float  g_maxE;
__device__ int    g_cnt[NTOK];
__device__ unsigned long long g_cand[NTOK * CAND_CAP];
__device__ int    g_idx[NTOK];
__device__ double g_partial[1024];

__device__ __forceinline__ uint32_t smem_u32(const void* p) {
    uint32_t a;
    asm("{ .reg .u64 t; cvta.to.shared.u64 t, %1; cvt.u32.u64 %0, t; }" : "=r"(a) : "l"(p));
    return a;
}
#define CP_ASYNC16(saddr, gptr) \
    asm volatile("cp.async.cg.shared.global [%0], [%1], 16;" :: "r"(saddr), "l"(gptr))
#define CP_COMMIT() asm volatile("cp.async.commit_group;" ::: "memory")
#define CP_WAIT1()  asm volatile("cp.async.wait_group 1;" ::: "memory")
#define LDSM_X4(r0, r1, r2, r3, a) \
    asm volatile("ldmatrix.sync.aligned.m8n8.x4.shared.b16 {%0,%1,%2,%3}, [%4];" \
        : "=r"(r0), "=r"(r1), "=r"(r2), "=r"(r3) : "r"(a))
#define MMA_F16(d, a, b0v, b1v) \
    asm volatile("mma.sync.aligned.m16n8k16.row.col.f32.f16.f16.f32 " \
        "{%0,%1,%2,%3}, {%4,%5,%6,%7}, {%8,%9}, {%0,%1,%2,%3};" \
        : "+f"((d)[0]), "+f"((d)[1]), "+f"((d)[2]), "+f"((d)[3]) \
        : "r"((a)[0]), "r"((a)[1]), "r"((a)[2]), "r"((a)[3]), "r"(b0v), "r"(b1v))

__device__ __forceinline__ uint32_t swaddr(int row, int u) {
    return (uint32_t)(row * 128 + ((u ^ (row & 7)) << 4));
}

// ---------------------------------------------------------------------------
// K0: codebook fp16 (pre-scaled by 2^10) + squared norms + per-block max norm
// ---------------------------------------------------------------------------
__global__ void k_prep_e(const float* __restrict__ E) {
    __shared__ float red[128];
    int k = blockIdx.x * blockDim.x + threadIdx.x;
    const float* e = E + (size_t)k * D;
    float s = 0.f;
    #pragma unroll 8
    for (int c = 0; c < D; c++) {
        float x = e[c];
        s = fmaf(x, x, s);
        g_Eh[(size_t)k * D + c] = __float2half_rn(x * ESCL);  // normal-range fp16
    }
    g_normE[k] = s;
    red[threadIdx.x] = s;
    __syncthreads();
    for (int o = 64; o > 0; o >>= 1) {
        if (threadIdx.x < o) red[threadIdx.x] = fmaxf(red[threadIdx.x], red[threadIdx.x + o]);
        __syncthreads();
    }
    if (threadIdx.x == 0) g_maxEblk[blockIdx.x] = red[0];
}

// ---------------------------------------------------------------------------
// K1: transpose X -> token-major (fp32 + fp16) + ||x||^2 + resets + maxE
// ---------------------------------------------------------------------------
__global__ void k_split_x(const float* __restrict__ X) {
    __shared__ float tile[D][33];
    __shared__ float psum[32][9];
    const int tid = threadIdx.x;
    const int b   = blockIdx.x >> 5;
    const int hw0 = (blockIdx.x & 31) * 32;
    const float* Xb = X + (size_t)b * (D * HW) + hw0;

    if (blockIdx.x == 0 && tid == 0) {       // finalize maxE (k_prep done: stream order)
        float m = 0.f;
        #pragma unroll
        for (int i = 0; i < 8; i++) m = fmaxf(m, g_maxEblk[i]);
        g_maxE = sqrtf(m);
    }
    if (tid < 32) g_cnt[b * HW + hw0 + tid] = 0;   // reset candidate counters

    {
        int w = tid >> 5, lane = tid & 31;
        #pragma unroll
        for (int c = w; c < D; c += 8) tile[c][lane] = Xb[(size_t)c * HW + lane];
    }
    __syncthreads();

    const int tt = tid >> 3;          // token 0..31
    const int cc = tid & 7;           // channel block
    const int n  = b * HW + hw0 + tt;
    float s = 0.f;
    #pragma unroll
    for (int c8 = 0; c8 < 4; c8++) {
        uint32_t hp[4];
        float xf[8];
        #pragma unroll
        for (int q = 0; q < 4; q++) {
            int c0 = cc * 32 + c8 * 8 + q * 2;
            float x0 = tile[c0][tt], x1 = tile[c0 + 1][tt];
            xf[q * 2] = x0; xf[q * 2 + 1] = x1;
            s = fmaf(x0, x0, s); s = fmaf(x1, x1, s);
            __half h0 = __float2half_rn(x0), h1 = __float2half_rn(x1);
            hp[q] = (uint32_t)*(uint16_t*)&h0 | ((uint32_t)*(uint16_t*)&h1 << 16);
        }
        *(uint4*)&g_Xh[(size_t)n * D + cc * 32 + c8 * 8] = make_uint4(hp[0], hp[1], hp[2], hp[3]);
        *(float4*)&g_Xt[(size_t)n * D + cc * 32 + c8 * 8] = make_float4(xf[0], xf[1], xf[2], xf[3]);
        *(float4*)&g_Xt[(size_t)n * D + cc * 32 + c8 * 8 + 4] = make_float4(xf[4], xf[5], xf[6], xf[7]);
    }
    psum[tt][cc] = s;
    __syncthreads();
    if (cc == 0) {
        float t = 0.f;
        #pragma unroll
        for (int q = 0; q < 8; q++) t += psum[tt][q];
        g_normX[n] = t;
    }
}

// ---------------------------------------------------------------------------
// K2: hh HMMA GEMM (K=256, E pre-scaled) + candidate collection in window
// ---------------------------------------------------------------------------
__global__ void __launch_bounds__(256, 2) k_vq()
{
    extern __shared__ char smem[];                 // NSTG * (A 16KB | B 16KB)
    __shared__ unsigned long long bestS[TM];
    __shared__ float nXs[TM], nEs[TN];

    const int tid  = threadIdx.x;
    const int bid  = blockIdx.x;
    const int tokenBase = (bid >> 3) * TM;
    const int codeBase  = (bid & 7) * TN;

    if (tid < TM) {
        bestS[tid] = ~0ull;
        nXs[tid] = g_normX[tokenBase + tid];
        nEs[tid] = g_normE[codeBase + tid];
    }

    const uint32_t sb = smem_u32(smem);
    const int ldr = tid >> 3, lds = tid & 7;

    auto issue = [&](int s) {
        const int koff = s * KCH;
        const uint32_t Ab = sb + (s % NSTG) * STG_BYTES;
        const uint32_t Bb = Ab + 16384;
        #pragma unroll
        for (int i = 0; i < 4; i++) {
            int r = ldr + i * 32;
            uint32_t so = swaddr(r, lds);
            CP_ASYNC16(Ab + so, g_Xh + (size_t)(tokenBase + r) * D + koff + lds * 8);
            CP_ASYNC16(Bb + so, g_Eh + (size_t)(codeBase  + r) * D + koff + lds * 8);
        }
        CP_COMMIT();
    };

    issue(0); issue(1);

    const int lane = tid & 31, wid = tid >> 5;
    const int mrow0 = (wid & 1) * 64;
    const int ncol0 = (wid >> 1) * 32;
    const int lrow  = lane & 15, lhalf = lane >> 4;

    float acc[4][4][4];
    #pragma unroll
    for (int m = 0; m < 4; m++)
        #pragma unroll
        for (int n = 0; n < 4; n++)
            #pragma unroll
            for (int q = 0; q < 4; q++) acc[m][n][q] = 0.f;

    for (int s = 0; s < NITER; s++) {
        CP_WAIT1();
        __syncthreads();
        if (s + 2 < NITER) issue(s + 2);

        const uint32_t Ab = sb + (s % NSTG) * STG_BYTES;
        const uint32_t Bb = Ab + 16384;

        #pragma unroll
        for (int k16 = 0; k16 < 4; k16++) {
            const int u = k16 * 2 + lhalf;
            uint32_t a[4][4], bfr[2][4];
            #pragma unroll
            for (int m = 0; m < 4; m++) {
                int r = mrow0 + m * 16 + lrow;
                LDSM_X4(a[m][0], a[m][1], a[m][2], a[m][3], Ab + swaddr(r, u));
            }
            #pragma unroll
            for (int nb = 0; nb < 2; nb++) {
                int r = ncol0 + nb * 16 + lrow;
                LDSM_X4(bfr[nb][0], bfr[nb][1], bfr[nb][2], bfr[nb][3], Bb + swaddr(r, u));
            }
            #pragma unroll
            for (int m = 0; m < 4; m++)
                #pragma unroll
                for (int n = 0; n < 4; n++)
                    MMA_F16(acc[m][n], a[m], bfr[n >> 1][n & 1], bfr[n >> 1][2 + (n & 1)]);
        }
    }

    // ---- pass 1: CTA-local packed argmin per token (undo 2^10 E scale)
    #pragma unroll
    for (int m = 0; m < 4; m++) {
        #pragma unroll
        for (int rr = 0; rr < 2; rr++) {
            const int row = mrow0 + m * 16 + (lane >> 2) + rr * 8;
            const float nX = nXs[row];
            unsigned long long key = ~0ull;
            #pragma unroll
            for (int n = 0; n < 4; n++) {
                #pragma unroll
                for (int cc2 = 0; cc2 < 2; cc2++) {
                    const int col = ncol0 + n * 8 + 2 * (lane & 3) + cc2;
                    float sdot = __fmul_rn(acc[m][n][rr * 2 + cc2], ESCL_INV); // exact
                    float d = __fadd_rn(__fsub_rn(nX, __fmul_rn(2.0f, sdot)), nEs[col]);
                    unsigned long long kk =
                        ((unsigned long long)__float_as_uint(d) << 32) |
                        (unsigned)(codeBase + col);
                    key = (kk < key) ? kk : key;
                }
            }
            atomicMin(&bestS[row], key);
        }
    }
    __syncthreads();

    // ---- pass 2: append candidates within 2T of CTA-local min
    const float mE = g_maxE;
    #pragma unroll
    for (int m = 0; m < 4; m++) {
        #pragma unroll
        for (int rr = 0; rr < 2; rr++) {
            const int row = mrow0 + m * 16 + (lane >> 2) + rr * 8;
            const float nX = nXs[row];
            const float dmin = __uint_as_float((uint32_t)(bestS[row] >> 32));
            const float T = fmaf(T_COEF * sqrtf(nX), mE, T_SLACK);
            const float thr = dmin + 2.0f * T;
            const int nglob = tokenBase + row;
            #pragma unroll
            for (int n = 0; n < 4; n++) {
                #pragma unroll
                for (int cc2 = 0; cc2 < 2; cc2++) {
                    const int col = ncol0 + n * 8 + 2 * (lane & 3) + cc2;
                    float sdot = __fmul_rn(acc[m][n][rr * 2 + cc2], ESCL_INV);
                    float d = __fadd_rn(__fsub_rn(nX, __fmul_rn(2.0f, sdot)), nEs[col]);
                    if (d <= thr) {
                        int slot = atomicAdd(&g_cnt[nglob], 1);
                        if (slot < CAND_CAP)
                            g_cand[(size_t)nglob * CAND_CAP + slot] =
                                ((unsigned long long)__float_as_uint(d) << 32) |
                                (unsigned)(codeBase + col);
                    }
                }
            }
        }
    }
}

// ---------------------------------------------------------------------------
// K3: exact refine — warp per token
// ---------------------------------------------------------------------------
__global__ void k_refine(const float* __restrict__ E)
{
    const int lane = threadIdx.x & 31;
    const int n = blockIdx.x * 8 + (threadIdx.x >> 5);
    const float nX = g_normX[n];
    const float T = fmaf(T_COEF * sqrtf(nX), g_maxE, T_SLACK);
    const int cnt = g_cnt[n];
    unsigned long long best = ~0ull;

    if (cnt <= CAND_CAP) {
        unsigned long long c = (lane < cnt) ? g_cand[(size_t)n * CAND_CAP + lane] : ~0ull;
        unsigned long long mn = c;
        #pragma unroll
        for (int o = 16; o > 0; o >>= 1) {
            unsigned long long t = __shfl_xor_sync(0xFFFFFFFFu, mn, o);
            mn = (t < mn) ? t : mn;
        }
        const float dmin = __uint_as_float((uint32_t)(mn >> 32));
        const float thr = dmin + 2.0f * T;
        const bool keep = (lane < cnt) &&
                          (__uint_as_float((uint32_t)(c >> 32)) <= thr);
        unsigned mask = __ballot_sync(0xFFFFFFFFu, keep);
        if (__popc(mask) == 1) {
            best = mn;                      // unique candidate: provably the argmin
        } else {
            const float* xr = g_Xt + (size_t)n * D;
            unsigned mm = mask;
            while (mm) {
                int b = __ffs(mm) - 1; mm &= mm - 1;
                int kk = (int)__shfl_sync(0xFFFFFFFFu, (unsigned)(c & 0xFFFFFFFFu), b);
                const float* er = E + (size_t)kk * D;
                float p = 0.f;
                #pragma unroll
                for (int j = 0; j < 8; j++)
                    p = fmaf(xr[lane * 8 + j], er[lane * 8 + j], p);
                #pragma unroll
                for (int o = 16; o > 0; o >>= 1) p += __shfl_xor_sync(0xFFFFFFFFu, p, o);
                float d = __fadd_rn(__fsub_rn(nX, __fmul_rn(2.0f, p)), g_normE[kk]);
                unsigned long long key =
                    ((unsigned long long)__float_as_uint(d) << 32) | (unsigned)kk;
                best = (key < best) ? key : best;
            }
        }
    } else {
        // overflow fallback: exact full scan (essentially never taken)
        const float* xr = g_Xt + (size_t)n * D;
        for (int k0 = lane; k0 < K; k0 += 32) {
            const float* er = E + (size_t)k0 * D;
            float p = 0.f;
            for (int j = 0; j < D; j++) p = fmaf(xr[j], er[j], p);
            float d = __fadd_rn(__fsub_rn(nX, __fmul_rn(2.0f, p)), g_normE[k0]);
            unsigned long long key =
                ((unsigned long long)__float_as_uint(d) << 32) | (unsigned)k0;
            best = (key < best) ? key : best;
        }
        #pragma unroll
        for (int o = 16; o > 0; o >>= 1) {
            unsigned long long t = __shfl_xor_sync(0xFFFFFFFFu, best, o);
            best = (t < best) ? t : best;
        }
    }
    if (lane == 0) g_idx[n] = (int)(best & 0xFFFFFFFFu);
}

// ---------------------------------------------------------------------------
// K4: gather (with reference x+(q-x) rounding) + idx out + MSE partials
// ---------------------------------------------------------------------------
__global__ void k_gather(const float* __restrict__ X, const float* __restrict__ E,
                         float* __restrict__ Q, int writeQ,
                         float* __restrict__ outIdxF, int writeIdx)
{
    __shared__ double sred[256];
    const int tid = threadIdx.x;
    const int cb  = blockIdx.x >> 7;
    const int n   = (blockIdx.x & 127) * 256 + tid;
    const int b   = n >> 10;
    const int hw  = n & (HW - 1);
    const int ch0 = cb * 32;
    const float* xb = X + (size_t)b * (D * HW) + (size_t)ch0 * HW + hw;
    float*       qb = Q + (size_t)b * (D * HW) + (size_t)ch0 * HW + hw;
    const int idx = g_idx[n];
    const float* e = E + (size_t)idx * D + ch0;

    if (writeIdx && cb == 0) outIdxF[n] = (float)idx;

    double s = 0.0;
    #pragma unroll
    for (int c4 = 0; c4 < 8; c4++) {
        float4 q4 = *(const float4*)(e + c4 * 4);
        float qv[4] = {q4.x, q4.y, q4.z, q4.w};
        #pragma unroll
        for (int j = 0; j < 4; j++) {
            int c = c4 * 4 + j;
            float x = xb[(size_t)c * HW];
            float dd = __fsub_rn(qv[j], x);
            if (writeQ) qb[(size_t)c * HW] = __fadd_rn(x, dd);   // ref straight-through
            s = fma((double)dd, (double)dd, s);
        }
    }
    sred[tid] = s;
    __syncthreads();
    for (int off = 128; off > 0; off >>= 1) {
        if (tid < off) sred[tid] += sred[tid + off];
        __syncthreads();
    }
    if (tid == 0) g_partial[blockIdx.x] = sred[0];
}

__global__ void k_loss(float* __restrict__ out, int lossOff)
{
    __shared__ double sd[256];
    int t = threadIdx.x;
    double s = 0.0;
    #pragma unroll
    for (int i = 0; i < 4; i++) s += g_partial[t * 4 + i];
    sd[t] = s;
    __syncthreads();
    for (int o = 128; o > 0; o >>= 1) {
        if (t < o) sd[t] += sd[t + o];
        __syncthreads();
    }
    if (t == 0) {
        float e = (float)(sd[0] / (double)((size_t)NTOK * D));
        out[lossOff] = e + 0.25f * e;
    }
}

// ---------------------------------------------------------------------------
extern "C" void kernel_launch(void* const* d_in, const int* in_sizes, int n_in,
                              void* d_out, int out_size)
{
    const float* X = (const float*)d_in[0];   // [32,256,32,32]
    const float* E = (const float*)d_in[1];   // [1024,256]
    float* out = (float*)d_out;

    const int qn = NTOK * D;
    int writeQ = 0, lossOff = -1, idxOff = -1;
    if (out_size >= qn) writeQ = 1;
    if (out_size == qn + 1 + NTOK) { lossOff = qn; idxOff = qn + 1; }
    else if (out_size == qn + 1)   { lossOff = qn; }
    else if (out_size == qn + NTOK){ idxOff = qn; }
    else if (out_size == NTOK)     { idxOff = 0; writeQ = 0; }

    cudaFuncSetAttribute(k_vq, cudaFuncAttributeMaxDynamicSharedMemorySize,
                         NSTG * STG_BYTES);

    k_prep_e<<<8, 128>>>(E);
    k_split_x<<<NTOK / 32, 256>>>(X);
    k_vq<<<(NTOK / TM) * (K / TN), 256, NSTG * STG_BYTES>>>();
    k_refine<<<NTOK / 8, 256>>>(E);
    k_gather<<<1024, 256>>>(X, E, out, writeQ,
                            (idxOff >= 0) ? (out + idxOff) : out,
                            (idxOff >= 0) ? 1 : 0);
    if (lossOff >= 0)
        k_loss<<<1, 256>>>(out, lossOff);
}

// round 8
// speedup vs baseline: 2.4471x; 1.0174x over previous
#include <cuda_runtime.h>
#include <cuda_fp16.h>
#include <math_constants.h>
#include <cstdint>

// ---------------- problem constants ----------------
#define NTOK 32768      // 32*32*32 tokens
#define D    256        // embedding dim
#define K    1024       // codebook size
#define HW   1024       // H*W
#define TM   128        // tokens per CTA tile
#define TN   128        // codes per CTA tile
#define KCH  64         // dims per pipeline stage
#define NITER 4         // 4 chunks of 64 dims (hh only)
#define NSTG 3          // cp.async stages
#define STG_BYTES 32768 // A 16KB + B 16KB per stage
#define CAND_CAP 32
#define ESCL      1024.0f          // 2^10 exact
#define ESCL_INV  9.765625e-4f     // 2^-10 exact
// |d_hh - d_exact| <= 4*2^-11*||x||*||e||max + slack
#define T_COEF  1.98e-3f
#define T_SLACK 2.0e-4f

// ---------------- device scratch (no allocations allowed) ----------------
__device__ __align__(256) __half g_Xh[NTOK * D];
__device__ __align__(256) __half g_Eh[K * D];      // fl16(e * 2^10)
__device__ float  g_normX[NTOK];
__device__ float  g_normE[K];
__device__ float  g_maxEblk[8];
__device__ float  g_maxE;
__device__ int    g_cnt[NTOK];
__device__ unsigned long long g_cand[NTOK * CAND_CAP];
__device__ int    g_idx[NTOK];
__device__ double g_partial[1024];

__device__ __forceinline__ uint32_t smem_u32(const void* p) {
    uint32_t a;
    asm("{ .reg .u64 t; cvta.to.shared.u64 t, %1; cvt.u32.u64 %0, t; }" : "=r"(a) : "l"(p));
    return a;
}
#define CP_ASYNC16(saddr, gptr) \
    asm volatile("cp.async.cg.shared.global [%0], [%1], 16;" :: "r"(saddr), "l"(gptr))
#define CP_COMMIT() asm volatile("cp.async.commit_group;" ::: "memory")
#define CP_WAIT1()  asm volatile("cp.async.wait_group 1;" ::: "memory")
#define LDSM_X4(r0, r1, r2, r3, a) \
    asm volatile("ldmatrix.sync.aligned.m8n8.x4.shared.b16 {%0,%1,%2,%3}, [%4];" \
        : "=r"(r0), "=r"(r1), "=r"(r2), "=r"(r3) : "r"(a))
#define MMA_F16(d, a, b0v, b1v) \
    asm volatile("mma.sync.aligned.m16n8k16.row.col.f32.f16.f16.f32 " \
        "{%0,%1,%2,%3}, {%4,%5,%6,%7}, {%8,%9}, {%0,%1,%2,%3};" \
        : "+f"((d)[0]), "+f"((d)[1]), "+f"((d)[2]), "+f"((d)[3]) \
        : "r"((a)[0]), "r"((a)[1]), "r"((a)[2]), "r"((a)[3]), "r"(b0v), "r"(b1v))

__device__ __forceinline__ uint32_t swaddr(int row, int u) {
    return (uint32_t)(row * 128 + ((u ^ (row & 7)) << 4));
}

// ---------------------------------------------------------------------------
// K0: codebook fp16 (pre-scaled by 2^10) + squared norms + per-block max norm
// ---------------------------------------------------------------------------
__global__ void k_prep_e(const float* __restrict__ E) {
    __shared__ float red[128];
    int k = blockIdx.x * blockDim.x + threadIdx.x;
    const float* e = E + (size_t)k * D;
    float s = 0.f;
    #pragma unroll 8
    for (int c = 0; c < D; c++) {
        float x = e[c];
        s = fmaf(x, x, s);
        g_Eh[(size_t)k * D + c] = __float2half_rn(x * ESCL);  // normal-range fp16
    }
    g_normE[k] = s;
    red[threadIdx.x] = s;
    __syncthreads();
    for (int o = 64; o > 0; o >>= 1) {
        if (threadIdx.x < o) red[threadIdx.x] = fmaxf(red[threadIdx.x], red[threadIdx.x + o]);
        __syncthreads();
    }
    if (threadIdx.x == 0) g_maxEblk[blockIdx.x] = red[0];
}

// ---------------------------------------------------------------------------
// K1: transpose X -> token-major fp16 (coalesced via smem staging) + ||x||^2
// ---------------------------------------------------------------------------
__global__ void k_split_x(const float* __restrict__ X) {
    __shared__ float tile[D][33];
    __shared__ float psum[32][9];
    __shared__ uint4 hbuf[32][32];    // 32 tokens x 32 x 16B chunks (full rows)
    const int tid = threadIdx.x;
    const int b   = blockIdx.x >> 5;
    const int hw0 = (blockIdx.x & 31) * 32;
    const float* Xb = X + (size_t)b * (D * HW) + hw0;

    if (blockIdx.x == 0 && tid == 0) {       // finalize maxE (k_prep done: stream order)
        float m = 0.f;
        #pragma unroll
        for (int i = 0; i < 8; i++) m = fmaxf(m, g_maxEblk[i]);
        g_maxE = sqrtf(m);
    }
    if (tid < 32) g_cnt[b * HW + hw0 + tid] = 0;   // reset candidate counters

    {
        int w = tid >> 5, lane = tid & 31;
        #pragma unroll
        for (int c = w; c < D; c += 8) tile[c][lane] = Xb[(size_t)c * HW + lane];
    }
    __syncthreads();

    const int tt = tid >> 3;          // token 0..31
    const int cc = tid & 7;           // channel block (32 channels)
    float s = 0.f;
    #pragma unroll
    for (int c8 = 0; c8 < 4; c8++) {
        uint32_t hp[4];
        #pragma unroll
        for (int q = 0; q < 4; q++) {
            int c0 = cc * 32 + c8 * 8 + q * 2;
            float x0 = tile[c0][tt], x1 = tile[c0 + 1][tt];
            s = fmaf(x0, x0, s); s = fmaf(x1, x1, s);
            __half h0 = __float2half_rn(x0), h1 = __float2half_rn(x1);
            hp[q] = (uint32_t)*(uint16_t*)&h0 | ((uint32_t)*(uint16_t*)&h1 << 16);
        }
        hbuf[tt][cc * 4 + c8] = make_uint4(hp[0], hp[1], hp[2], hp[3]);
    }
    psum[tt][cc] = s;
    __syncthreads();

    // coalesced write: each warp stores one full 512B token row per iteration
    {
        const int w = tid >> 5, lane = tid & 31;
        uint4* dst = (uint4*)g_Xh;
        #pragma unroll
        for (int t = 0; t < 4; t++) {
            int token = t * 8 + w;
            dst[(size_t)(b * HW + hw0 + token) * 32 + lane] = hbuf[token][lane];
        }
    }
    if (cc == 0) {
        float t = 0.f;
        #pragma unroll
        for (int q = 0; q < 8; q++) t += psum[tt][q];
        g_normX[b * HW + hw0 + tt] = t;
    }
}

// ---------------------------------------------------------------------------
// K2: hh HMMA GEMM (K=256, E pre-scaled) + candidate collection in window
// ---------------------------------------------------------------------------
__global__ void __launch_bounds__(256, 2) k_vq()
{
    extern __shared__ char smem[];                 // NSTG * (A 16KB | B 16KB)
    __shared__ unsigned long long bestS[TM];
    __shared__ float nXs[TM], nEs[TN];

    const int tid  = threadIdx.x;
    const int bid  = blockIdx.x;
    const int tokenBase = (bid >> 3) * TM;
    const int codeBase  = (bid & 7) * TN;

    if (tid < TM) {
        bestS[tid] = ~0ull;
        nXs[tid] = g_normX[tokenBase + tid];
        nEs[tid] = g_normE[codeBase + tid];
    }

    const uint32_t sb = smem_u32(smem);
    const int ldr = tid >> 3, lds = tid & 7;

    auto issue = [&](int s) {
        const int koff = s * KCH;
        const uint32_t Ab = sb + (s % NSTG) * STG_BYTES;
        const uint32_t Bb = Ab + 16384;
        #pragma unroll
        for (int i = 0; i < 4; i++) {
            int r = ldr + i * 32;
            uint32_t so = swaddr(r, lds);
            CP_ASYNC16(Ab + so, g_Xh + (size_t)(tokenBase + r) * D + koff + lds * 8);
            CP_ASYNC16(Bb + so, g_Eh + (size_t)(codeBase  + r) * D + koff + lds * 8);
        }
        CP_COMMIT();
    };

    issue(0); issue(1);

    const int lane = tid & 31, wid = tid >> 5;
    const int mrow0 = (wid & 1) * 64;
    const int ncol0 = (wid >> 1) * 32;
    const int lrow  = lane & 15, lhalf = lane >> 4;

    float acc[4][4][4];
    #pragma unroll
    for (int m = 0; m < 4; m++)
        #pragma unroll
        for (int n = 0; n < 4; n++)
            #pragma unroll
            for (int q = 0; q < 4; q++) acc[m][n][q] = 0.f;

    for (int s = 0; s < NITER; s++) {
        CP_WAIT1();
        __syncthreads();
        if (s + 2 < NITER) issue(s + 2);

        const uint32_t Ab = sb + (s % NSTG) * STG_BYTES;
        const uint32_t Bb = Ab + 16384;

        #pragma unroll
        for (int k16 = 0; k16 < 4; k16++) {
            const int u = k16 * 2 + lhalf;
            uint32_t a[4][4], bfr[2][4];
            #pragma unroll
            for (int m = 0; m < 4; m++) {
                int r = mrow0 + m * 16 + lrow;
                LDSM_X4(a[m][0], a[m][1], a[m][2], a[m][3], Ab + swaddr(r, u));
            }
            #pragma unroll
            for (int nb = 0; nb < 2; nb++) {
                int r = ncol0 + nb * 16 + lrow;
                LDSM_X4(bfr[nb][0], bfr[nb][1], bfr[nb][2], bfr[nb][3], Bb + swaddr(r, u));
            }
            #pragma unroll
            for (int m = 0; m < 4; m++)
                #pragma unroll
                for (int n = 0; n < 4; n++)
                    MMA_F16(acc[m][n], a[m], bfr[n >> 1][n & 1], bfr[n >> 1][2 + (n & 1)]);
        }
    }

    // ---- pass 1: CTA-local packed argmin per token (undo 2^10 E scale)
    #pragma unroll
    for (int m = 0; m < 4; m++) {
        #pragma unroll
        for (int rr = 0; rr < 2; rr++) {
            const int row = mrow0 + m * 16 + (lane >> 2) + rr * 8;
            const float nX = nXs[row];
            unsigned long long key = ~0ull;
            #pragma unroll
            for (int n = 0; n < 4; n++) {
                #pragma unroll
                for (int cc2 = 0; cc2 < 2; cc2++) {
                    const int col = ncol0 + n * 8 + 2 * (lane & 3) + cc2;
                    float sdot = __fmul_rn(acc[m][n][rr * 2 + cc2], ESCL_INV); // exact
                    float d = __fadd_rn(__fsub_rn(nX, __fmul_rn(2.0f, sdot)), nEs[col]);
                    unsigned long long kk =
                        ((unsigned long long)__float_as_uint(d) << 32) |
                        (unsigned)(codeBase + col);
                    key = (kk < key) ? kk : key;
                }
            }
            atomicMin(&bestS[row], key);
        }
    }
    __syncthreads();

    // ---- pass 2: append candidates within 2T of CTA-local min
    const float mE = g_maxE;
    #pragma unroll
    for (int m = 0; m < 4; m++) {
        #pragma unroll
        for (int rr = 0; rr < 2; rr++) {
            const int row = mrow0 + m * 16 + (lane >> 2) + rr * 8;
            const float nX = nXs[row];
            const float dmin = __uint_as_float((uint32_t)(bestS[row] >> 32));
            const float T = fmaf(T_COEF * sqrtf(nX), mE, T_SLACK);
            const float thr = dmin + 2.0f * T;
            const int nglob = tokenBase + row;
            #pragma unroll
            for (int n = 0; n < 4; n++) {
                #pragma unroll
                for (int cc2 = 0; cc2 < 2; cc2++) {
                    const int col = ncol0 + n * 8 + 2 * (lane & 3) + cc2;
                    float sdot = __fmul_rn(acc[m][n][rr * 2 + cc2], ESCL_INV);
                    float d = __fadd_rn(__fsub_rn(nX, __fmul_rn(2.0f, sdot)), nEs[col]);
                    if (d <= thr) {
                        int slot = atomicAdd(&g_cnt[nglob], 1);
                        if (slot < CAND_CAP)
                            g_cand[(size_t)nglob * CAND_CAP + slot] =
                                ((unsigned long long)__float_as_uint(d) << 32) |
                                (unsigned)(codeBase + col);
                    }
                }
            }
        }
    }
}

// ---------------------------------------------------------------------------
// K3: exact refine — warp per token; x row staged from NCHW on demand
// ---------------------------------------------------------------------------
__global__ void k_refine(const float* __restrict__ E, const float* __restrict__ X)
{
    __shared__ float xs[8][256];
    const int lane = threadIdx.x & 31;
    const int w    = threadIdx.x >> 5;
    const int n = blockIdx.x * 8 + w;
    const float nX = g_normX[n];
    const float T = fmaf(T_COEF * sqrtf(nX), g_maxE, T_SLACK);
    const int cnt = g_cnt[n];
    unsigned long long best = ~0ull;

    const int b  = n >> 10;
    const int hw = n & (HW - 1);
    const float* xsrc = X + (size_t)b * (D * HW) + hw;

    if (cnt <= CAND_CAP) {
        unsigned long long c = (lane < cnt) ? g_cand[(size_t)n * CAND_CAP + lane] : ~0ull;
        unsigned long long mn = c;
        #pragma unroll
        for (int o = 16; o > 0; o >>= 1) {
            unsigned long long t = __shfl_xor_sync(0xFFFFFFFFu, mn, o);
            mn = (t < mn) ? t : mn;
        }
        const float dmin = __uint_as_float((uint32_t)(mn >> 32));
        const float thr = dmin + 2.0f * T;
        const bool keep = (lane < cnt) &&
                          (__uint_as_float((uint32_t)(c >> 32)) <= thr);
        unsigned mask = __ballot_sync(0xFFFFFFFFu, keep);
        if (__popc(mask) == 1) {
            best = mn;                      // unique candidate: provably the argmin
        } else {
            #pragma unroll
            for (int j = 0; j < 8; j++)     // stage x row (warp-local)
                xs[w][lane * 8 + j] = xsrc[(size_t)(lane * 8 + j) * HW];
            __syncwarp();
            unsigned mm = mask;
            while (mm) {
                int bb = __ffs(mm) - 1; mm &= mm - 1;
                int kk = (int)__shfl_sync(0xFFFFFFFFu, (unsigned)(c & 0xFFFFFFFFu), bb);
                const float* er = E + (size_t)kk * D;
                float p = 0.f;
                #pragma unroll
                for (int j = 0; j < 8; j++)
                    p = fmaf(xs[w][lane * 8 + j], er[lane * 8 + j], p);
                #pragma unroll
                for (int o = 16; o > 0; o >>= 1) p += __shfl_xor_sync(0xFFFFFFFFu, p, o);
                float d = __fadd_rn(__fsub_rn(nX, __fmul_rn(2.0f, p)), g_normE[kk]);
                unsigned long long key =
                    ((unsigned long long)__float_as_uint(d) << 32) | (unsigned)kk;
                best = (key < best) ? key : best;
            }
        }
    } else {
        // overflow fallback: exact full scan (essentially never taken)
        #pragma unroll
        for (int j = 0; j < 8; j++)
            xs[w][lane * 8 + j] = xsrc[(size_t)(lane * 8 + j) * HW];
        __syncwarp();
        for (int k0 = lane; k0 < K; k0 += 32) {
            const float* er = E + (size_t)k0 * D;
            float p = 0.f;
            for (int j = 0; j < D; j++) p = fmaf(xs[w][j], er[j], p);
            float d = __fadd_rn(__fsub_rn(nX, __fmul_rn(2.0f, p)), g_normE[k0]);
            unsigned long long key =
                ((unsigned long long)__float_as_uint(d) << 32) | (unsigned)k0;
            best = (key < best) ? key : best;
        }
        #pragma unroll
        for (int o = 16; o > 0; o >>= 1) {
            unsigned long long t = __shfl_xor_sync(0xFFFFFFFFu, best, o);
            best = (t < best) ? t : best;
        }
    }
    if (lane == 0) g_idx[n] = (int)(best & 0xFFFFFFFFu);
}

// ---------------------------------------------------------------------------
// K4: gather (with reference x+(q-x) rounding) + idx out + MSE partials
// ---------------------------------------------------------------------------
__global__ void k_gather(const float* __restrict__ X, const float* __restrict__ E,
                         float* __restrict__ Q, int writeQ,
                         float* __restrict__ outIdxF, int writeIdx)
{
    __shared__ double sred[256];
    const int tid = threadIdx.x;
    const int cb  = blockIdx.x >> 7;
    const int n   = (blockIdx.x & 127) * 256 + tid;
    const int b   = n >> 10;
    const int hw  = n & (HW - 1);
    const int ch0 = cb * 32;
    const float* xb = X + (size_t)b * (D * HW) + (size_t)ch0 * HW + hw;
    float*       qb = Q + (size_t)b * (D * HW) + (size_t)ch0 * HW + hw;
    const int idx = g_idx[n];
    const float* e = E + (size_t)idx * D + ch0;

    if (writeIdx && cb == 0) outIdxF[n] = (float)idx;

    double s = 0.0;
    #pragma unroll
    for (int c4 = 0; c4 < 8; c4++) {
        float4 q4 = *(const float4*)(e + c4 * 4);
        float qv[4] = {q4.x, q4.y, q4.z, q4.w};
        #pragma unroll
        for (int j = 0; j < 4; j++) {
            int c = c4 * 4 + j;
            float x = xb[(size_t)c * HW];
            float dd = __fsub_rn(qv[j], x);
            if (writeQ) qb[(size_t)c * HW] = __fadd_rn(x, dd);   // ref straight-through
            s = fma((double)dd, (double)dd, s);
        }
    }
    sred[tid] = s;
    __syncthreads();
    for (int off = 128; off > 0; off >>= 1) {
        if (tid < off) sred[tid] += sred[tid + off];
        __syncthreads();
    }
    if (tid == 0) g_partial[blockIdx.x] = sred[0];
}

__global__ void k_loss(float* __restrict__ out, int lossOff)
{
    __shared__ double sd[256];
    int t = threadIdx.x;
    double s = 0.0;
    #pragma unroll
    for (int i = 0; i < 4; i++) s += g_partial[t * 4 + i];
    sd[t] = s;
    __syncthreads();
    for (int o = 128; o > 0; o >>= 1) {
        if (t < o) sd[t] += sd[t + o];
        __syncthreads();
    }
    if (t == 0) {
        float e = (float)(sd[0] / (double)((size_t)NTOK * D));
        out[lossOff] = e + 0.25f * e;
    }
}

// ---------------------------------------------------------------------------
extern "C" void kernel_launch(void* const* d_in, const int* in_sizes, int n_in,
                              void* d_out, int out_size)
{
    const float* X = (const float*)d_in[0];   // [32,256,32,32]
    const float* E = (const float*)d_in[1];   // [1024,256]
    float* out = (float*)d_out;

    const int qn = NTOK * D;
    int writeQ = 0, lossOff = -1, idxOff = -1;
    if (out_size >= qn) writeQ = 1;
    if (out_size == qn + 1 + NTOK) { lossOff = qn; idxOff = qn + 1; }
    else if (out_size == qn + 1)   { lossOff = qn; }
    else if (out_size == qn + NTOK){ idxOff = qn; }
    else if (out_size == NTOK)     { idxOff = 0; writeQ = 0; }

    cudaFuncSetAttribute(k_vq, cudaFuncAttributeMaxDynamicSharedMemorySize,
                         NSTG * STG_BYTES);

    k_prep_e<<<8, 128>>>(E);
    k_split_x<<<NTOK / 32, 256>>>(X);
    k_vq<<<(NTOK / TM) * (K / TN), 256, NSTG * STG_BYTES>>>();
    k_refine<<<NTOK / 8, 256>>>(E, X);
    k_gather<<<1024, 256>>>(X, E, out, writeQ,
                            (idxOff >= 0) ? (out + idxOff) : out,
                            (idxOff >= 0) ? 1 : 0);
    if (lossOff >= 0)
        k_loss<<<1, 256>>>(out, lossOff);
}